// round 5
// baseline (speedup 1.0000x reference)
#include <cuda_runtime.h>
#include <cuda_bf16.h>

// Problem constants (S=8192, G=1024, T=4096, E=16384)
#define E_N 16384
#define T_N 4096
#define G_N 1024
#define CHUNK 32
#define NCHUNKS 128
#define NSUB 8
#define SUBCAP 256
#define NBLK 128
#define NTHR 1024

// cdiff TRANSPOSED: [group][chunk] -> phase-B rows contiguous (LDG.128/lane).
__device__ float g_cdiff[G_N * NCHUNKS];   // zeroed at load; re-zeroed phase B
// carry: [chunk][group] -> phase-C reads warp-coalesced.
__device__ float g_carry[NCHUNKS * G_N];
// Per-(chunk,sub) boundary lists: {row<<10 | group, w_bits}
__device__ int2  g_list[NCHUNKS * NSUB * SUBCAP];
__device__ int   g_count[NCHUNKS * NSUB];  // zeroed at load; re-zeroed phase C

// Grid barrier state: generation counter is monotonic across graph replays.
__device__ unsigned g_bar_arrive;          // zero-init; reset by releaser
__device__ volatile unsigned g_bar_gen;

__device__ __forceinline__ void grid_barrier() {
    __threadfence();          // publish this thread's prior writes/atomics
    __syncthreads();
    if (threadIdx.x == 0) {
        unsigned gen = g_bar_gen;
        if (atomicAdd(&g_bar_arrive, 1) == NBLK - 1) {
            g_bar_arrive = 0;
            __threadfence();
            g_bar_gen = gen + 1;          // release
        } else {
            while (g_bar_gen == gen) { }  // L2-latency-paced poll
        }
    }
    __syncthreads();
    __threadfence();          // acquire: see other SMs' writes
}

// ---------------------------------------------------------------------------
// One persistent kernel: 128 blocks x 1024 threads x 128 KB smem
// (1 CTA/SM, single wave -> spin barrier is safe).
// ---------------------------------------------------------------------------
__global__ void __launch_bounds__(NTHR, 1)
fused_kernel(const int*   __restrict__ index,
             const float* __restrict__ rate,
             const float* __restrict__ start,
             const float* __restrict__ endt,
             const float* __restrict__ t0,
             const int*   __restrict__ group_id,
             const float* __restrict__ weights,
             float*       __restrict__ out) {
    extern __shared__ float smem[];        // 32768 floats = 128 KB
    __shared__ int s_cnt[NSUB];
    const int tid = threadIdx.x;
    const int blk = blockIdx.x;

    // ---------------- Phase A: event preprocess + binning -----------------
    // t0 -> smem (1 float4 per thread; 16 KB at smem[0..4095])
    ((float4*)smem)[tid] = ((const float4*)t0)[tid];

    const bool active = tid < 128;
    const int e = blk * 128 + tid;
    float st = 0.f, en = 0.f, rt = 0.f, wsc = 0.f;
    int src = 0, g = 0;
    if (active) {                          // hoisted: overlap with preload
        st  = __ldg(&start[e]);
        en  = __ldg(&endt[e]);
        src = __ldg(&index[e]);
        rt  = __ldg(&rate[e]);
        wsc = __ldg(&weights[src]);
        g   = __ldg(&group_id[src]);
    }
    __syncthreads();

    if (active) {
        // Branchless lower_bound (t0 sorted, 4096 = 2^12), dual interleaved.
        int a = 0, b = 0;
        #pragma unroll
        for (int s = T_N >> 1; s; s >>= 1) {
            a += (smem[a + s - 1] < st) ? s : 0;
            b += (smem[b + s - 1] < en) ? s : 0;
        }
        a += (smem[a] < st) ? 1 : 0;       // ts
        b += (smem[b] < en) ? 1 : 0;       // te

        const int ts = a, te = b;
        if (te > ts) {                     // active at least one timestep
            const float w = rt * wsc;

            // Chunk-level diff (transposed), fire-and-forget REDG.
            const int c0 = (ts + CHUNK - 1) >> 5;
            const int c1 = (te + CHUNK - 1) >> 5;
            if (c0 != c1) {
                if (c0 < NCHUNKS) atomicAdd(&g_cdiff[g * NCHUNKS + c0],  w);
                if (c1 < NCHUNKS) atomicAdd(&g_cdiff[g * NCHUNKS + c1], -w);
            }

            // Interior row boundaries -> 8-way split per-chunk lists.
            const int sub = e & (NSUB - 1);
            const int rs = ts & (CHUNK - 1);
            const int re = te & (CHUNK - 1);
            if (rs != 0) {
                const int bin = (ts >> 5) * NSUB + sub;
                int idx = atomicAdd(&g_count[bin], 1);
                if (idx < SUBCAP)
                    g_list[bin * SUBCAP + idx] =
                        make_int2((rs << 10) | g, __float_as_int(w));
            }
            if (re != 0 && te < T_N) {
                const int bin = (te >> 5) * NSUB + sub;
                int idx = atomicAdd(&g_count[bin], 1);
                if (idx < SUBCAP)
                    g_list[bin * SUBCAP + idx] =
                        make_int2((re << 10) | g, __float_as_int(-w));
            }
        }
    }

    // Overlap the phase-C smem zero with barrier skew (t0 no longer needed
    // after the local sync below).
    __syncthreads();
    {
        float4* d4 = (float4*)smem;
        const float4 z = make_float4(0.f, 0.f, 0.f, 0.f);
        #pragma unroll
        for (int i = 0; i < (CHUNK * G_N / 4) / NTHR; i++)   // 8 each
            d4[i * NTHR + tid] = z;
    }

    grid_barrier();   // all cdiff / list atomics globally visible

    // ---------------- Phase B: chunk-level prefix -> carry -----------------
    // Warp per group: lane owns 4 consecutive chunks of the contiguous row.
    {
        const int wid = tid >> 5, lid = tid & 31;
        if (wid < 8) {
            const int grp = blk * 8 + wid;
            float4 v = ((float4*)g_cdiff)[grp * (NCHUNKS / 4) + lid];
            const float s1 = v.x, s2 = s1 + v.y, s3 = s2 + v.z, s4 = s3 + v.w;
            float sum = s4;                       // warp inclusive scan
            #pragma unroll
            for (int o = 1; o < 32; o <<= 1) {
                float n = __shfl_up_sync(0xffffffffu, sum, o);
                if (lid >= o) sum += n;
            }
            const float off = sum - s4;           // exclusive prefix
            const int c = lid * 4;
            g_carry[(c + 0) * G_N + grp] = off + s1;
            g_carry[(c + 1) * G_N + grp] = off + s2;
            g_carry[(c + 2) * G_N + grp] = off + s3;
            g_carry[(c + 3) * G_N + grp] = off + s4;
            ((float4*)g_cdiff)[grp * (NCHUNKS / 4) + lid] =
                make_float4(0.f, 0.f, 0.f, 0.f);  // clean for next replay
        }
        if (tid < NSUB) {
            int n = g_count[blk * NSUB + tid];    // prefetch counts (post-bar A)
            s_cnt[tid] = n < SUBCAP ? n : SUBCAP;
        }
    }

    grid_barrier();   // carry + lists globally visible

    // ---------------- Phase C: per-chunk emit ------------------------------
    // Block = chunk. Scatter ~200 boundary entries into the (pre-zeroed)
    // 32x1024 smem diff tile, then per-group serial prefix + coalesced STG.
    {
        const int tbeg = blk * CHUNK;
        #pragma unroll
        for (int s = 0; s < NSUB; s++) {
            const int n = s_cnt[s];
            const int2* lst = &g_list[(blk * NSUB + s) * SUBCAP];
            for (int i = tid; i < n; i += NTHR) {
                int2 ev = lst[i];
                atomicAdd(&smem[(ev.x >> 10) * G_N + (ev.x & (G_N - 1))],
                          __int_as_float(ev.y));
            }
        }
        __syncthreads();

        float acc = g_carry[blk * G_N + tid];
        #pragma unroll
        for (int r = 0; r < CHUNK; r++) {
            acc += smem[r * G_N + tid];           // row 0 always 0
            out[(size_t)(tbeg + r) * G_N + tid] = acc;
        }

        __syncthreads();
        if (tid < NSUB) g_count[blk * NSUB + tid] = 0;  // clean for replay
    }
}

// ---------------------------------------------------------------------------
extern "C" void kernel_launch(void* const* d_in, const int* in_sizes, int n_in,
                              void* d_out, int out_size) {
    const int*   index    = (const int*)  d_in[0];
    const float* rate     = (const float*)d_in[1];
    const float* start    = (const float*)d_in[2];
    const float* endt     = (const float*)d_in[3];
    const float* t0       = (const float*)d_in[4];
    const int*   group_id = (const int*)  d_in[5];
    const float* weights  = (const float*)d_in[6];
    float* out = (float*)d_out;

    cudaFuncSetAttribute(fused_kernel,
                         cudaFuncAttributeMaxDynamicSharedMemorySize,
                         CHUNK * G_N * (int)sizeof(float));

    fused_kernel<<<NBLK, NTHR, CHUNK * G_N * (int)sizeof(float)>>>(
        index, rate, start, endt, t0, group_id, weights, out);
}

// round 6
// speedup vs baseline: 1.2224x; 1.2224x over previous
#include <cuda_runtime.h>
#include <cuda_bf16.h>

// Problem constants (S=8192, G=1024, T=4096, E=16384)
#define E_N 16384
#define T_N 4096
#define G_N 1024
#define CHUNK 32
#define NCHUNKS 128
#define NBLK 128
#define NTHR 1024

// Row-granular diff image [T][G] (16 MB, L2-resident). Only ~31K entries are
// ever nonzero; phase C zero-stores its slice after reading (replay-clean).
__device__ float g_rowdiff[T_N * G_N];
// Chunk-granular diff, TRANSPOSED [group][chunk] for contiguous phase-B rows.
__device__ float g_cdiff[G_N * NCHUNKS];
// Carry at each chunk start, [chunk][group] (phase-C reads warp-coalesced).
__device__ float g_carry[NCHUNKS * G_N];

// Grid barrier (sense via monotonic generation counter -> replay-safe).
__device__ unsigned g_bar_arrive;
__device__ volatile unsigned g_bar_gen;

__device__ __forceinline__ void grid_barrier() {
    __threadfence();
    __syncthreads();
    if (threadIdx.x == 0) {
        unsigned gen = g_bar_gen;
        if (atomicAdd(&g_bar_arrive, 1) == NBLK - 1) {
            g_bar_arrive = 0;
            __threadfence();
            g_bar_gen = gen + 1;           // release
        } else {
            while (g_bar_gen == gen) { }   // poll
        }
    }
    __syncthreads();
    __threadfence();
}

// ---------------------------------------------------------------------------
// One persistent kernel: 128 blocks x 1024 threads (single wave on 148 SMs).
// ---------------------------------------------------------------------------
__global__ void __launch_bounds__(NTHR, 1)
fused_kernel(const int*   __restrict__ index,
             const float* __restrict__ rate,
             const float* __restrict__ start,
             const float* __restrict__ endt,
             const float* __restrict__ t0,
             const int*   __restrict__ group_id,
             const float* __restrict__ weights,
             float*       __restrict__ out) {
    __shared__ float s_t0[T_N];            // 16 KB
    const int tid = threadIdx.x;
    const int blk = blockIdx.x;

    // ---------------- Phase A: event preprocess + diff scatter -------------
    ((float4*)s_t0)[tid] = ((const float4*)t0)[tid];  // 1 float4/thread

    const bool active = tid < 128;
    const int e = blk * 128 + tid;
    float st = 0.f, en = 0.f, rt = 0.f, wsc = 0.f;
    int g = 0;
    if (active) {                           // hoisted, overlap with preload
        st = __ldg(&start[e]);
        en = __ldg(&endt[e]);
        int src = __ldg(&index[e]);
        rt  = __ldg(&rate[e]);
        wsc = __ldg(&weights[src]);
        g   = __ldg(&group_id[src]);
    }
    __syncthreads();

    if (active) {
        // Branchless dual lower_bound over sorted t0 (4096 = 2^12).
        int a = 0, b = 0;
        #pragma unroll
        for (int s = T_N >> 1; s; s >>= 1) {
            a += (s_t0[a + s - 1] < st) ? s : 0;
            b += (s_t0[b + s - 1] < en) ? s : 0;
        }
        a += (s_t0[a] < st) ? 1 : 0;        // ts
        b += (s_t0[b] < en) ? 1 : 0;        // te

        const int ts = a, te = b;
        if (te > ts) {
            const float w = rt * wsc;
            // Chunk-level: +w at first fully-covered chunk, -w at first
            // uncovered chunk. Fire-and-forget RED (result unused).
            const int c0 = (ts + CHUNK - 1) >> 5;
            const int c1 = (te + CHUNK - 1) >> 5;
            if (c0 != c1) {
                if (c0 < NCHUNKS) atomicAdd(&g_cdiff[g * NCHUNKS + c0],  w);
                if (c1 < NCHUNKS) atomicAdd(&g_cdiff[g * NCHUNKS + c1], -w);
            }
            // Interior row boundaries straight into the row image. RED.
            if (ts & (CHUNK - 1))
                atomicAdd(&g_rowdiff[ts * G_N + g],  w);
            if ((te & (CHUNK - 1)) && te < T_N)
                atomicAdd(&g_rowdiff[te * G_N + g], -w);
        }
    }

    grid_barrier();   // all RED scatters globally visible

    // Prefetch this block's 32 rowdiff rows (column g = tid) while phase B
    // runs; data is valid after barrier 1. Coalesced 128B/warp per row.
    const int tbeg = blk * CHUNK;
    float v[CHUNK];
    #pragma unroll
    for (int r = 0; r < CHUNK; r++)
        v[r] = g_rowdiff[(tbeg + r) * G_N + tid];

    // ---------------- Phase B: chunk-level prefix -> carry -----------------
    // Warp per group: lane owns 4 consecutive chunks of a contiguous row.
    {
        const int wid = tid >> 5, lid = tid & 31;
        if (wid < 8) {
            const int grp = blk * 8 + wid;
            float4 c4 = ((float4*)g_cdiff)[grp * (NCHUNKS / 4) + lid];
            const float s1 = c4.x, s2 = s1 + c4.y, s3 = s2 + c4.z, s4 = s3 + c4.w;
            float sum = s4;                 // warp inclusive scan of lane sums
            #pragma unroll
            for (int o = 1; o < 32; o <<= 1) {
                float n = __shfl_up_sync(0xffffffffu, sum, o);
                if (lid >= o) sum += n;
            }
            const float off = sum - s4;     // exclusive prefix
            const int c = lid * 4;
            g_carry[(c + 0) * G_N + grp] = off + s1;
            g_carry[(c + 1) * G_N + grp] = off + s2;
            g_carry[(c + 2) * G_N + grp] = off + s3;
            g_carry[(c + 3) * G_N + grp] = off + s4;
            ((float4*)g_cdiff)[grp * (NCHUNKS / 4) + lid] =
                make_float4(0.f, 0.f, 0.f, 0.f);   // clean for next replay
        }
    }

    grid_barrier();   // carry globally visible

    // ---------------- Phase C: scan + emit ---------------------------------
    // Thread owns column g = tid of chunk blk. Serial register scan with the
    // carry as base, coalesced output stores, zero-store rowdiff behind.
    {
        float acc = g_carry[blk * G_N + tid];
        #pragma unroll
        for (int r = 0; r < CHUNK; r++) {
            acc += v[r];                    // row 0 contribution always 0
            out[(size_t)(tbeg + r) * G_N + tid] = acc;
        }
        #pragma unroll
        for (int r = 0; r < CHUNK; r++)
            g_rowdiff[(tbeg + r) * G_N + tid] = 0.0f;  // replay-clean
    }
}

// ---------------------------------------------------------------------------
extern "C" void kernel_launch(void* const* d_in, const int* in_sizes, int n_in,
                              void* d_out, int out_size) {
    const int*   index    = (const int*)  d_in[0];
    const float* rate     = (const float*)d_in[1];
    const float* start    = (const float*)d_in[2];
    const float* endt     = (const float*)d_in[3];
    const float* t0       = (const float*)d_in[4];
    const int*   group_id = (const int*)  d_in[5];
    const float* weights  = (const float*)d_in[6];
    float* out = (float*)d_out;

    fused_kernel<<<NBLK, NTHR>>>(index, rate, start, endt, t0,
                                 group_id, weights, out);
}